// round 6
// baseline (speedup 1.0000x reference)
#include <cuda_runtime.h>
#include <cstdint>
#include <math.h>

#define DD 1024
#define TT 4096
#define BB 4
#define EPSF 1e-6f

#define BM 128
#define BN 64            // per weight matrix; one head per block in out_kernel
#define BK 32
#define NCHUNK (DD/BK)   // 32
#define NSTAGE 3

#define A_TILE_B  (BM*BK*4)                 // 16384
#define B_TILE_B  (BN*BK*4)                 // 8192
#define STAGE_B   (A_TILE_B + 2*B_TILE_B)   // 32768
#define OFF_STATS (NSTAGE*STAGE_B)          // 98304
#define SMEM_TOTAL (OFF_STATS + 2048)       // 100352

#define NRB (BB*TT/BM)   // 128 row blocks

// Deterministic two-stage reduction buffers
__device__ float g_pk  [NRB*DD];
__device__ float g_pkv [NRB*DD];
__device__ float g_ksum [BB*DD];
__device__ float g_kvsum[BB*DD];
// tf32-rounded copies (rounded once; GEMMs consume raw bits, no per-use cvt)
__device__ __align__(16) float g_Xr [BB*TT*DD];
__device__ __align__(16) float g_Wqr[DD*DD];
__device__ __align__(16) float g_Wkr[DD*DD];
__device__ __align__(16) float g_Wvr[DD*DD];
__device__ __align__(16) float g_Wgr[DD*DD];

// ---------------------------------------------------------------- helpers ---
__device__ __forceinline__ uint32_t smem_u32(const void* p) {
    uint32_t a;
    asm("{ .reg .u64 t; cvta.to.shared.u64 t, %1; cvt.u32.u64 %0, t; }" : "=r"(a) : "l"(p));
    return a;
}
__device__ __forceinline__ void cp16(uint32_t dst, const void* src) {
    asm volatile("cp.async.cg.shared.global [%0], [%1], 16;" :: "r"(dst), "l"(src));
}
__device__ __forceinline__ void cp_commit() { asm volatile("cp.async.commit_group;" ::: "memory"); }
template <int N> __device__ __forceinline__ void cp_wait() {
    asm volatile("cp.async.wait_group %0;" :: "n"(N) : "memory");
}
__device__ __forceinline__ float rna_tf32(float f) {
    uint32_t o;
    asm("cvt.rna.tf32.f32 %0, %1;" : "=r"(o) : "f"(f));
    return __uint_as_float(o);
}
__device__ __forceinline__ void mma_tf32(float* d, const uint32_t* a, const uint32_t* b) {
    asm volatile("mma.sync.aligned.m16n8k8.row.col.f32.tf32.tf32.f32 "
                 "{%0,%1,%2,%3}, {%4,%5,%6,%7}, {%8,%9}, {%0,%1,%2,%3};"
                 : "+f"(d[0]), "+f"(d[1]), "+f"(d[2]), "+f"(d[3])
                 : "r"(a[0]), "r"(a[1]), "r"(a[2]), "r"(a[3]), "r"(b[0]), "r"(b[1]));
}
__device__ __forceinline__ float phi_f(float x) { return x > 0.f ? x + 1.f : __expf(x); }
__device__ __forceinline__ float sigm(float x) { return 1.f / (1.f + __expf(-x)); }

// Swizzled smem index (in uint32 units) for logical (row, k), 32-float rows.
// 16B groups XORed with (row&7): conflict-free for both staging and fragments.
__device__ __forceinline__ int sw_idx(int row, int k) {
    return row * 32 + ((((k >> 2) ^ (row & 7)) << 2) | (k & 3));
}

// Load tiles of one K-chunk into a stage: A 128x32, B1 64x32, B2 64x32 (fp32)
__device__ __forceinline__ void load_stage(uint32_t sbase,
                                           const float* A, const float* B1, const float* B2,
                                           int tid)
{
#pragma unroll
    for (int p = 0; p < 4; p++) {           // A: 1024 float4 / 256 thr
        int idx = p * 256 + tid;
        int row = idx >> 3, cg = idx & 7;
        cp16(sbase + row * 128 + ((cg ^ (row & 7)) << 4),
             (const char*)A + (size_t)row * (DD*4) + cg * 16);
    }
#pragma unroll
    for (int p = 0; p < 2; p++) {           // B1: 512 float4
        int idx = p * 256 + tid;
        int row = idx >> 3, cg = idx & 7;
        cp16(sbase + A_TILE_B + row * 128 + ((cg ^ (row & 7)) << 4),
             (const char*)B1 + (size_t)row * (DD*4) + cg * 16);
    }
#pragma unroll
    for (int p = 0; p < 2; p++) {           // B2: 512 float4
        int idx = p * 256 + tid;
        int row = idx >> 3, cg = idx & 7;
        cp16(sbase + A_TILE_B + B_TILE_B + row * 128 + ((cg ^ (row & 7)) << 4),
             (const char*)B2 + (size_t)row * (DD*4) + cg * 16);
    }
}

// 3-stage double-output GEMM mainloop. Inputs are pre-rounded tf32 bits.
// acc1/acc2: [2 m][4 nt][4 regs]. Warp layout: wm = wid&3 (M), wn = wid>>2 (N).
__device__ __forceinline__ void run_gemm2(char* smem, uint32_t sb,
                                          const float* A, const float* B1, const float* B2,
                                          int tid, float acc1[2][4][4], float acc2[2][4][4])
{
    const int wid = tid >> 5, lane = tid & 31;
    const int wm = wid & 3, wn = wid >> 2;
    const int l4 = lane >> 2, lm4 = lane & 3;

#pragma unroll
    for (int m = 0; m < 2; m++)
#pragma unroll
        for (int nt = 0; nt < 4; nt++)
#pragma unroll
            for (int r = 0; r < 4; r++) { acc1[m][nt][r] = 0.f; acc2[m][nt][r] = 0.f; }

    load_stage(sb + 0*STAGE_B, A,      B1,      B2,      tid); cp_commit();
    load_stage(sb + 1*STAGE_B, A + BK, B1 + BK, B2 + BK, tid); cp_commit();

    for (int c = 0; c < NCHUNK; c++) {
        const int s = c % NSTAGE;
        // Wait until the oldest outstanding group (stage c) has landed:
        // <=1 pending when 2 prefetches are in flight, all-drain at the tail.
        if (c + 2 < NCHUNK) cp_wait<1>(); else cp_wait<0>();
        __syncthreads();
        if (c + 2 < NCHUNK) {
            const int k0 = (c + 2) * BK;
            load_stage(sb + ((c + 2) % NSTAGE) * STAGE_B, A + k0, B1 + k0, B2 + k0, tid);
            cp_commit();
        }

        const uint32_t* As  = (const uint32_t*)(smem + s * STAGE_B);
        const uint32_t* B1s = (const uint32_t*)(smem + s * STAGE_B + A_TILE_B);
        const uint32_t* B2s = (const uint32_t*)(smem + s * STAGE_B + A_TILE_B + B_TILE_B);

#pragma unroll
        for (int kk = 0; kk < 4; kk++) {
            const int kc = kk * 8;
            uint32_t af[2][4];
#pragma unroll
            for (int m = 0; m < 2; m++) {
                const int r0 = wm * 32 + m * 16 + l4;
                af[m][0] = As[sw_idx(r0,     kc + lm4)];
                af[m][1] = As[sw_idx(r0 + 8, kc + lm4)];
                af[m][2] = As[sw_idx(r0,     kc + lm4 + 4)];
                af[m][3] = As[sw_idx(r0 + 8, kc + lm4 + 4)];
            }
            uint32_t bf1[4][2], bf2[4][2];
#pragma unroll
            for (int nt = 0; nt < 4; nt++) {
                const int n0 = wn * 32 + nt * 8 + l4;
                bf1[nt][0] = B1s[sw_idx(n0, kc + lm4)];
                bf1[nt][1] = B1s[sw_idx(n0, kc + lm4 + 4)];
                bf2[nt][0] = B2s[sw_idx(n0, kc + lm4)];
                bf2[nt][1] = B2s[sw_idx(n0, kc + lm4 + 4)];
            }
#pragma unroll
            for (int m = 0; m < 2; m++)
#pragma unroll
                for (int nt = 0; nt < 4; nt++) {
                    mma_tf32(acc1[m][nt], af[m], bf1[nt]);
                    mma_tf32(acc2[m][nt], af[m], bf2[nt]);
                }
        }
        __syncthreads();
    }
}

// ---------------------------------------------------------------------------
// Kernel 0: round fp32 -> tf32 bits (once per tensor)
// ---------------------------------------------------------------------------
__global__ void round_kernel(const float4* __restrict__ src, float4* __restrict__ dst, int n4) {
    int i = blockIdx.x * blockDim.x + threadIdx.x;
    if (i >= n4) return;
    float4 v = src[i];
    v.x = rna_tf32(v.x); v.y = rna_tf32(v.y); v.z = rna_tf32(v.z); v.w = rna_tf32(v.w);
    dst[i] = v;
}

// ---------------------------------------------------------------------------
// Kernel 1: K=phi(X@Wk^T), V=X@Wv^T; per-rowblock column sums of phi(K), phi(K)*V
// grid = (DD/BN=16, NRB=128), 256 threads
// ---------------------------------------------------------------------------
__global__ void __launch_bounds__(256)
stats_kernel(const float* __restrict__ X, const float* __restrict__ Wk,
             const float* __restrict__ Wv)
{
    extern __shared__ char smem[];
    uint32_t sb = smem_u32(smem);
    const int tid = threadIdx.x;
    const int row0 = blockIdx.y * BM, col0 = blockIdx.x * BN;

    float accK[2][4][4], accV[2][4][4];
    run_gemm2(smem, sb, X + (size_t)row0 * DD, Wk + (size_t)col0 * DD,
              Wv + (size_t)col0 * DD, tid, accK, accV);

    // Stage phi(K) and phi(K)*V into smem [128][66]
    float* stA = (float*)smem;               // [128][66]
    float* stB = stA + 128 * 66;             // [128][66]
    const int wid = tid >> 5, lane = tid & 31;
    const int wm = wid & 3, wn = wid >> 2;
    const int l4 = lane >> 2, lm4 = lane & 3;

#pragma unroll
    for (int m = 0; m < 2; m++)
#pragma unroll
        for (int nt = 0; nt < 4; nt++) {
            const int col = wn * 32 + nt * 8 + lm4 * 2;
#pragma unroll
            for (int half = 0; half < 2; half++) {
                const int row = wm * 32 + m * 16 + l4 + half * 8;
#pragma unroll
                for (int cc = 0; cc < 2; cc++) {
                    float kv = phi_f(accK[m][nt][half * 2 + cc]);
                    stA[row * 66 + col + cc] = kv;
                    stB[row * 66 + col + cc] = kv * accV[m][nt][half * 2 + cc];
                }
            }
        }
    __syncthreads();

    // Column reduce: 4 quarters of 32 rows, then fold
    float* partA = (float*)(smem + OFF_STATS);        // [4][64]
    float* partB = partA + 256;                       // [4][64]
    {
        const int col = tid & 63, q = tid >> 6;
        float sa = 0.f, sv = 0.f;
#pragma unroll
        for (int r = 0; r < 32; r++) {
            const int row = q * 32 + r;
            sa += stA[row * 66 + col];
            sv += stB[row * 66 + col];
        }
        partA[q * 64 + col] = sa;
        partB[q * 64 + col] = sv;
    }
    __syncthreads();
    if (tid < 64) {
        float sa = partA[tid] + partA[64 + tid] + partA[128 + tid] + partA[192 + tid];
        float sv = partB[tid] + partB[64 + tid] + partB[128 + tid] + partB[192 + tid];
        size_t o = (size_t)blockIdx.y * DD + col0 + tid;
        g_pk[o]  = sa;
        g_pkv[o] = sv;
    }
}

// ---------------------------------------------------------------------------
// Kernel 2: fold 32 row-block partials per batch
// ---------------------------------------------------------------------------
__global__ void reduce_stats_kernel() {
    int i = blockIdx.x * blockDim.x + threadIdx.x;
    if (i >= BB * DD) return;
    int b = i >> 10, d = i & 1023;
    float sk = 0.f, skv = 0.f;
    int rb0 = b * (NRB / BB);
    for (int rb = 0; rb < NRB / BB; rb++) {
        sk  += g_pk [(size_t)(rb0 + rb) * DD + d];
        skv += g_pkv[(size_t)(rb0 + rb) * DD + d];
    }
    g_ksum[i]  = sk;
    g_kvsum[i] = skv;
}

// ---------------------------------------------------------------------------
// Kernel 3: Q=phi(X@Wq^T), G=X@Wg^T; s,z per row; gated output.
// grid = (16, 128); block column == one head (BN = HD = 64).
// ---------------------------------------------------------------------------
__global__ void __launch_bounds__(256)
out_kernel(const float* __restrict__ Xr, const float* __restrict__ Wq,
           const float* __restrict__ Wg, const float* __restrict__ bgv,
           const float* __restrict__ X, float* __restrict__ out)
{
    extern __shared__ char smem[];
    uint32_t sb = smem_u32(smem);
    const int tid = threadIdx.x;
    const int row0 = blockIdx.y * BM, col0 = blockIdx.x * BN;
    const int b = row0 / TT;

    // Dedicated (non-aliased) stats region
    float* kvsS  = (float*)(smem + OFF_STATS);   // [64]
    float* ksS   = kvsS + 64;                    // [64]
    float* bgS   = ksS + 64;                     // [64]
    float* ratio = bgS + 64;                     // [128]
    if (tid < 64) {
        kvsS[tid] = g_kvsum[b * DD + col0 + tid];
        ksS[tid]  = g_ksum [b * DD + col0 + tid];
        bgS[tid]  = bgv[col0 + tid];
    }
    __syncthreads();

    float accQ[2][4][4], accG[2][4][4];
    run_gemm2(smem, sb, Xr + (size_t)row0 * DD, Wq + (size_t)col0 * DD,
              Wg + (size_t)col0 * DD, tid, accQ, accG);

    const int wid = tid >> 5, lane = tid & 31;
    const int wm = wid & 3, wn = wid >> 2;
    const int l4 = lane >> 2, lm4 = lane & 3;

    // Partial s,z per (row, thread-slice): 8 partials per row
    float* red_s = (float*)smem;          // [128][8]
    float* red_z = red_s + 128 * 8;       // [128][8]
    const int sl = wn * 4 + lm4;
#pragma unroll
    for (int m = 0; m < 2; m++)
#pragma unroll
        for (int half = 0; half < 2; half++) {
            const int row = wm * 32 + m * 16 + l4 + half * 8;
            float s = 0.f, z = 0.f;
#pragma unroll
            for (int nt = 0; nt < 4; nt++) {
                const int col = wn * 32 + nt * 8 + lm4 * 2;
#pragma unroll
                for (int cc = 0; cc < 2; cc++) {
                    float q = phi_f(accQ[m][nt][half * 2 + cc]);
                    s += q * kvsS[col + cc];
                    z += q * ksS[col + cc];
                }
            }
            red_s[row * 8 + sl] = s;
            red_z[row * 8 + sl] = z;
        }
    __syncthreads();
    if (tid < 128) {
        float s = 0.f, z = 0.f;
#pragma unroll
        for (int j = 0; j < 8; j++) { s += red_s[tid * 8 + j]; z += red_z[tid * 8 + j]; }
        ratio[tid] = s / (z + EPSF);
    }
    __syncthreads();

    // Gate + mix, direct float2 stores (uses ORIGINAL X for the mix)
#pragma unroll
    for (int m = 0; m < 2; m++)
#pragma unroll
        for (int half = 0; half < 2; half++) {
            const int row = wm * 32 + m * 16 + l4 + half * 8;
            const float rt = ratio[row];
            const size_t rbase = (size_t)(row0 + row) * DD + col0;
#pragma unroll
            for (int nt = 0; nt < 4; nt++) {
                const int col = wn * 32 + nt * 8 + lm4 * 2;
                const float2 x2 = *(const float2*)&X[rbase + col];
                float g0 = sigm(accG[m][nt][half * 2 + 0] + bgS[col + 0]);
                float g1 = sigm(accG[m][nt][half * 2 + 1] + bgS[col + 1]);
                float2 o;
                o.x = g0 * rt + (1.f - g0) * x2.x;
                o.y = g1 * rt + (1.f - g1) * x2.y;
                *(float2*)&out[rbase + col] = o;
            }
        }
}

// ---------------------------------------------------------------------------
extern "C" void kernel_launch(void* const* d_in, const int* in_sizes, int n_in,
                              void* d_out, int out_size)
{
    const float* x  = (const float*)d_in[0];
    const float* Wq = (const float*)d_in[1];
    const float* Wk = (const float*)d_in[2];
    const float* Wv = (const float*)d_in[3];
    // d_in[4] = Wo — unused by the reference computation
    const float* Wg = (const float*)d_in[5];
    const float* bg = (const float*)d_in[6];
    float* out = (float*)d_out;

    cudaFuncSetAttribute(stats_kernel, cudaFuncAttributeMaxDynamicSharedMemorySize, SMEM_TOTAL);
    cudaFuncSetAttribute(out_kernel,   cudaFuncAttributeMaxDynamicSharedMemorySize, SMEM_TOTAL);

    float *Xr, *Wqr, *Wkr, *Wvr, *Wgr;
    cudaGetSymbolAddress((void**)&Xr,  g_Xr);
    cudaGetSymbolAddress((void**)&Wqr, g_Wqr);
    cudaGetSymbolAddress((void**)&Wkr, g_Wkr);
    cudaGetSymbolAddress((void**)&Wvr, g_Wvr);
    cudaGetSymbolAddress((void**)&Wgr, g_Wgr);

    const int nX4 = BB*TT*DD/4, nW4 = DD*DD/4;
    round_kernel<<<(nX4 + 255)/256, 256>>>((const float4*)x,  (float4*)Xr,  nX4);
    round_kernel<<<(nW4 + 255)/256, 256>>>((const float4*)Wq, (float4*)Wqr, nW4);
    round_kernel<<<(nW4 + 255)/256, 256>>>((const float4*)Wk, (float4*)Wkr, nW4);
    round_kernel<<<(nW4 + 255)/256, 256>>>((const float4*)Wv, (float4*)Wvr, nW4);
    round_kernel<<<(nW4 + 255)/256, 256>>>((const float4*)Wg, (float4*)Wgr, nW4);

    dim3 grid(DD / BN, NRB);   // (16, 128)
    stats_kernel<<<grid, 256, SMEM_TOTAL>>>(Xr, Wkr, Wvr);
    reduce_stats_kernel<<<(BB * DD + 255) / 256, 256>>>();
    out_kernel<<<grid, 256, SMEM_TOTAL>>>(Xr, Wqr, Wgr, bg, x, out);
}

// round 7
// speedup vs baseline: 2.2823x; 2.2823x over previous
#include <cuda_runtime.h>
#include <cuda_fp16.h>
#include <cstdint>
#include <math.h>

#define DD 1024
#define TT 4096
#define BB 4
#define EPSF 1e-6f

#define BM 128
#define BN 64            // per weight matrix; one head per block in out_kernel
#define BK 64            // halves per K-chunk (=128 bytes/row)
#define NCHUNK (DD/BK)   // 16

#define A_TILE_B  (BM*BK*2)                 // 16384
#define B_TILE_B  (BN*BK*2)                 // 8192
#define STAGE_B   (A_TILE_B + 2*B_TILE_B)   // 32768
#define OFF_STATS (128*66*4*2)              // 67584 (after epilogue staging)
#define SMEM_TOTAL (OFF_STATS + 2048)       // 69632

#define NRB (BB*TT/BM)   // 128 row blocks

// Deterministic two-stage reduction buffers
__device__ float g_pk  [NRB*DD];
__device__ float g_pkv [NRB*DD];
__device__ float g_ksum [BB*DD];
__device__ float g_kvsum[BB*DD];
// fp16 copies (converted once per launch)
__device__ __align__(16) __half g_Xh [BB*TT*DD];
__device__ __align__(16) __half g_Wqh[DD*DD];
__device__ __align__(16) __half g_Wkh[DD*DD];
__device__ __align__(16) __half g_Wvh[DD*DD];
__device__ __align__(16) __half g_Wgh[DD*DD];

// ---------------------------------------------------------------- helpers ---
__device__ __forceinline__ uint32_t smem_u32(const void* p) {
    uint32_t a;
    asm("{ .reg .u64 t; cvta.to.shared.u64 t, %1; cvt.u32.u64 %0, t; }" : "=r"(a) : "l"(p));
    return a;
}
__device__ __forceinline__ void cp16(uint32_t dst, const void* src) {
    asm volatile("cp.async.cg.shared.global [%0], [%1], 16;" :: "r"(dst), "l"(src));
}
__device__ __forceinline__ void cp_commit() { asm volatile("cp.async.commit_group;" ::: "memory"); }
template <int N> __device__ __forceinline__ void cp_wait() {
    asm volatile("cp.async.wait_group %0;" :: "n"(N) : "memory");
}
__device__ __forceinline__ void mma_f16(float* d, const uint32_t* a, const uint32_t* b) {
    asm volatile("mma.sync.aligned.m16n8k16.row.col.f32.f16.f16.f32 "
                 "{%0,%1,%2,%3}, {%4,%5,%6,%7}, {%8,%9}, {%0,%1,%2,%3};"
                 : "+f"(d[0]), "+f"(d[1]), "+f"(d[2]), "+f"(d[3])
                 : "r"(a[0]), "r"(a[1]), "r"(a[2]), "r"(a[3]), "r"(b[0]), "r"(b[1]));
}
__device__ __forceinline__ float phi_f(float x) { return x > 0.f ? x + 1.f : __expf(x); }
__device__ __forceinline__ float sigm(float x) { return 1.f / (1.f + __expf(-x)); }

// Swizzled u32 index into a tile of 128-byte rows (64 halves):
// 16B groups XORed with (row&7) — conflict-free for staging and fragments.
__device__ __forceinline__ int swh(int row, int byteoff) {
    return row * 32 + ((((byteoff >> 4) ^ (row & 7)) << 2) | ((byteoff & 15) >> 2));
}

// Load one K-chunk into a stage: A 128x64h, B1 64x64h, B2 64x64h
__device__ __forceinline__ void load_stage(uint32_t sbase,
                                           const __half* A, const __half* B1, const __half* B2,
                                           int tid)
{
#pragma unroll
    for (int p = 0; p < 4; p++) {           // A: 1024 x 16B
        int idx = p * 256 + tid;
        int row = idx >> 3, cg = idx & 7;
        cp16(sbase + row * 128 + ((cg ^ (row & 7)) << 4),
             (const char*)A + (size_t)row * (DD*2) + cg * 16);
    }
#pragma unroll
    for (int p = 0; p < 2; p++) {           // B1: 512 x 16B
        int idx = p * 256 + tid;
        int row = idx >> 3, cg = idx & 7;
        cp16(sbase + A_TILE_B + row * 128 + ((cg ^ (row & 7)) << 4),
             (const char*)B1 + (size_t)row * (DD*2) + cg * 16);
    }
#pragma unroll
    for (int p = 0; p < 2; p++) {           // B2: 512 x 16B
        int idx = p * 256 + tid;
        int row = idx >> 3, cg = idx & 7;
        cp16(sbase + A_TILE_B + B_TILE_B + row * 128 + ((cg ^ (row & 7)) << 4),
             (const char*)B2 + (size_t)row * (DD*2) + cg * 16);
    }
}

// 2-stage double-output fp16 GEMM mainloop (round-4-proven wait structure).
// acc1/acc2: [2 m][4 nt][4 regs]. Warp layout: wm = wid&3 (M), wn = wid>>2 (N).
__device__ __forceinline__ void run_gemm2(char* smem, uint32_t sb,
                                          const __half* A, const __half* B1, const __half* B2,
                                          int tid, float acc1[2][4][4], float acc2[2][4][4])
{
    const int wid = tid >> 5, lane = tid & 31;
    const int wm = wid & 3, wn = wid >> 2;
    const int l4 = lane >> 2, lm4 = lane & 3;

#pragma unroll
    for (int m = 0; m < 2; m++)
#pragma unroll
        for (int nt = 0; nt < 4; nt++)
#pragma unroll
            for (int r = 0; r < 4; r++) { acc1[m][nt][r] = 0.f; acc2[m][nt][r] = 0.f; }

    load_stage(sb, A, B1, B2, tid);
    cp_commit();

    for (int c = 0; c < NCHUNK; c++) {
        const int s = c & 1;
        if (c + 1 < NCHUNK) {
            const int k0 = (c + 1) * BK;
            load_stage(sb + ((c + 1) & 1) * STAGE_B, A + k0, B1 + k0, B2 + k0, tid);
            cp_commit();
            cp_wait<1>();
        } else {
            cp_wait<0>();
        }
        __syncthreads();

        const uint32_t* As  = (const uint32_t*)(smem + s * STAGE_B);
        const uint32_t* B1s = (const uint32_t*)(smem + s * STAGE_B + A_TILE_B);
        const uint32_t* B2s = (const uint32_t*)(smem + s * STAGE_B + A_TILE_B + B_TILE_B);

#pragma unroll
        for (int ks = 0; ks < 4; ks++) {             // 4 k16-steps per chunk
            const int bo = ks * 32 + lm4 * 4;        // byte offset of k pair
            uint32_t af[2][4];
#pragma unroll
            for (int m = 0; m < 2; m++) {
                const int r0 = wm * 32 + m * 16 + l4;
                af[m][0] = As[swh(r0,     bo)];
                af[m][1] = As[swh(r0 + 8, bo)];
                af[m][2] = As[swh(r0,     bo + 16)];
                af[m][3] = As[swh(r0 + 8, bo + 16)];
            }
            uint32_t bf1[4][2], bf2[4][2];
#pragma unroll
            for (int nt = 0; nt < 4; nt++) {
                const int n0 = wn * 32 + nt * 8 + l4;
                bf1[nt][0] = B1s[swh(n0, bo)];
                bf1[nt][1] = B1s[swh(n0, bo + 16)];
                bf2[nt][0] = B2s[swh(n0, bo)];
                bf2[nt][1] = B2s[swh(n0, bo + 16)];
            }
#pragma unroll
            for (int m = 0; m < 2; m++)
#pragma unroll
                for (int nt = 0; nt < 4; nt++) {
                    mma_f16(acc1[m][nt], af[m], bf1[nt]);
                    mma_f16(acc2[m][nt], af[m], bf2[nt]);
                }
        }
        __syncthreads();
    }
}

// ---------------------------------------------------------------------------
// Kernel 0: convert fp32 -> fp16 (once per tensor)
// ---------------------------------------------------------------------------
__global__ void cvt_kernel(const float4* __restrict__ src, uint2* __restrict__ dst, int n4) {
    int i = blockIdx.x * blockDim.x + threadIdx.x;
    if (i >= n4) return;
    float4 v = src[i];
    __half2 h0 = __floats2half2_rn(v.x, v.y);
    __half2 h1 = __floats2half2_rn(v.z, v.w);
    uint2 o;
    o.x = *(uint32_t*)&h0;
    o.y = *(uint32_t*)&h1;
    dst[i] = o;
}

// ---------------------------------------------------------------------------
// Kernel 1: K=phi(X@Wk^T), V=X@Wv^T; per-rowblock column sums of phi(K), phi(K)*V
// grid = (DD/BN=16, NRB=128), 256 threads
// ---------------------------------------------------------------------------
__global__ void __launch_bounds__(256)
stats_kernel(const __half* __restrict__ X, const __half* __restrict__ Wk,
             const __half* __restrict__ Wv)
{
    extern __shared__ char smem[];
    uint32_t sb = smem_u32(smem);
    const int tid = threadIdx.x;
    const int row0 = blockIdx.y * BM, col0 = blockIdx.x * BN;

    float accK[2][4][4], accV[2][4][4];
    run_gemm2(smem, sb, X + (size_t)row0 * DD, Wk + (size_t)col0 * DD,
              Wv + (size_t)col0 * DD, tid, accK, accV);

    // Stage phi(K) and phi(K)*V into smem [128][66]
    float* stA = (float*)smem;               // [128][66]
    float* stB = stA + 128 * 66;             // [128][66]
    const int wid = tid >> 5, lane = tid & 31;
    const int wm = wid & 3, wn = wid >> 2;
    const int l4 = lane >> 2, lm4 = lane & 3;

#pragma unroll
    for (int m = 0; m < 2; m++)
#pragma unroll
        for (int nt = 0; nt < 4; nt++) {
            const int col = wn * 32 + nt * 8 + lm4 * 2;
#pragma unroll
            for (int half = 0; half < 2; half++) {
                const int row = wm * 32 + m * 16 + l4 + half * 8;
#pragma unroll
                for (int cc = 0; cc < 2; cc++) {
                    float kv = phi_f(accK[m][nt][half * 2 + cc]);
                    stA[row * 66 + col + cc] = kv;
                    stB[row * 66 + col + cc] = kv * accV[m][nt][half * 2 + cc];
                }
            }
        }
    __syncthreads();

    // Column reduce: 4 quarters of 32 rows, then fold
    float* partA = (float*)(smem + OFF_STATS);        // [4][64]
    float* partB = partA + 256;                       // [4][64]
    {
        const int col = tid & 63, q = tid >> 6;
        float sa = 0.f, sv = 0.f;
#pragma unroll
        for (int r = 0; r < 32; r++) {
            const int row = q * 32 + r;
            sa += stA[row * 66 + col];
            sv += stB[row * 66 + col];
        }
        partA[q * 64 + col] = sa;
        partB[q * 64 + col] = sv;
    }
    __syncthreads();
    if (tid < 64) {
        float sa = partA[tid] + partA[64 + tid] + partA[128 + tid] + partA[192 + tid];
        float sv = partB[tid] + partB[64 + tid] + partB[128 + tid] + partB[192 + tid];
        size_t o = (size_t)blockIdx.y * DD + col0 + tid;
        g_pk[o]  = sa;
        g_pkv[o] = sv;
    }
}

// ---------------------------------------------------------------------------
// Kernel 2: fold 32 row-block partials per batch
// ---------------------------------------------------------------------------
__global__ void reduce_stats_kernel() {
    int i = blockIdx.x * blockDim.x + threadIdx.x;
    if (i >= BB * DD) return;
    int b = i >> 10, d = i & 1023;
    float sk = 0.f, skv = 0.f;
    int rb0 = b * (NRB / BB);
    for (int rb = 0; rb < NRB / BB; rb++) {
        sk  += g_pk [(size_t)(rb0 + rb) * DD + d];
        skv += g_pkv[(size_t)(rb0 + rb) * DD + d];
    }
    g_ksum[i]  = sk;
    g_kvsum[i] = skv;
}

// ---------------------------------------------------------------------------
// Kernel 3: Q=phi(X@Wq^T), G=X@Wg^T; s,z per row; gated output.
// grid = (16, 128); block column == one head (BN = HD = 64).
// ---------------------------------------------------------------------------
__global__ void __launch_bounds__(256)
out_kernel(const __half* __restrict__ Xh, const __half* __restrict__ Wq,
           const __half* __restrict__ Wg, const float* __restrict__ bgv,
           const float* __restrict__ X, float* __restrict__ out)
{
    extern __shared__ char smem[];
    uint32_t sb = smem_u32(smem);
    const int tid = threadIdx.x;
    const int row0 = blockIdx.y * BM, col0 = blockIdx.x * BN;
    const int b = row0 / TT;

    // Dedicated (non-aliased) stats region
    float* kvsS  = (float*)(smem + OFF_STATS);   // [64]
    float* ksS   = kvsS + 64;                    // [64]
    float* bgS   = ksS + 64;                     // [64]
    float* ratio = bgS + 64;                     // [128]
    if (tid < 64) {
        kvsS[tid] = g_kvsum[b * DD + col0 + tid];
        ksS[tid]  = g_ksum [b * DD + col0 + tid];
        bgS[tid]  = bgv[col0 + tid];
    }
    __syncthreads();

    float accQ[2][4][4], accG[2][4][4];
    run_gemm2(smem, sb, Xh + (size_t)row0 * DD, Wq + (size_t)col0 * DD,
              Wg + (size_t)col0 * DD, tid, accQ, accG);

    const int wid = tid >> 5, lane = tid & 31;
    const int wm = wid & 3, wn = wid >> 2;
    const int l4 = lane >> 2, lm4 = lane & 3;

    // Partial s,z per (row, thread-slice): 8 partials per row
    float* red_s = (float*)smem;          // [128][8]
    float* red_z = red_s + 128 * 8;       // [128][8]
    const int sl = wn * 4 + lm4;
#pragma unroll
    for (int m = 0; m < 2; m++)
#pragma unroll
        for (int half = 0; half < 2; half++) {
            const int row = wm * 32 + m * 16 + l4 + half * 8;
            float s = 0.f, z = 0.f;
#pragma unroll
            for (int nt = 0; nt < 4; nt++) {
                const int col = wn * 32 + nt * 8 + lm4 * 2;
#pragma unroll
                for (int cc = 0; cc < 2; cc++) {
                    float q = phi_f(accQ[m][nt][half * 2 + cc]);
                    s += q * kvsS[col + cc];
                    z += q * ksS[col + cc];
                }
            }
            red_s[row * 8 + sl] = s;
            red_z[row * 8 + sl] = z;
        }
    __syncthreads();
    if (tid < 128) {
        float s = 0.f, z = 0.f;
#pragma unroll
        for (int j = 0; j < 8; j++) { s += red_s[tid * 8 + j]; z += red_z[tid * 8 + j]; }
        ratio[tid] = s / (z + EPSF);
    }
    __syncthreads();

    // Gate + mix, direct float2 stores (uses ORIGINAL fp32 X for the mix)
#pragma unroll
    for (int m = 0; m < 2; m++)
#pragma unroll
        for (int half = 0; half < 2; half++) {
            const int row = wm * 32 + m * 16 + l4 + half * 8;
            const float rt = ratio[row];
            const size_t rbase = (size_t)(row0 + row) * DD + col0;
#pragma unroll
            for (int nt = 0; nt < 4; nt++) {
                const int col = wn * 32 + nt * 8 + lm4 * 2;
                const float2 x2 = *(const float2*)&X[rbase + col];
                float g0 = sigm(accG[m][nt][half * 2 + 0] + bgS[col + 0]);
                float g1 = sigm(accG[m][nt][half * 2 + 1] + bgS[col + 1]);
                float2 o;
                o.x = g0 * rt + (1.f - g0) * x2.x;
                o.y = g1 * rt + (1.f - g1) * x2.y;
                *(float2*)&out[rbase + col] = o;
            }
        }
}

// ---------------------------------------------------------------------------
extern "C" void kernel_launch(void* const* d_in, const int* in_sizes, int n_in,
                              void* d_out, int out_size)
{
    const float* x  = (const float*)d_in[0];
    const float* Wq = (const float*)d_in[1];
    const float* Wk = (const float*)d_in[2];
    const float* Wv = (const float*)d_in[3];
    // d_in[4] = Wo — unused by the reference computation
    const float* Wg = (const float*)d_in[5];
    const float* bg = (const float*)d_in[6];
    float* out = (float*)d_out;

    cudaFuncSetAttribute(stats_kernel, cudaFuncAttributeMaxDynamicSharedMemorySize, SMEM_TOTAL);
    cudaFuncSetAttribute(out_kernel,   cudaFuncAttributeMaxDynamicSharedMemorySize, SMEM_TOTAL);

    __half *Xh, *Wqh, *Wkh, *Wvh, *Wgh;
    cudaGetSymbolAddress((void**)&Xh,  g_Xh);
    cudaGetSymbolAddress((void**)&Wqh, g_Wqh);
    cudaGetSymbolAddress((void**)&Wkh, g_Wkh);
    cudaGetSymbolAddress((void**)&Wvh, g_Wvh);
    cudaGetSymbolAddress((void**)&Wgh, g_Wgh);

    const int nX4 = BB*TT*DD/4, nW4 = DD*DD/4;
    cvt_kernel<<<(nX4 + 255)/256, 256>>>((const float4*)x,  (uint2*)Xh,  nX4);
    cvt_kernel<<<(nW4 + 255)/256, 256>>>((const float4*)Wq, (uint2*)Wqh, nW4);
    cvt_kernel<<<(nW4 + 255)/256, 256>>>((const float4*)Wk, (uint2*)Wkh, nW4);
    cvt_kernel<<<(nW4 + 255)/256, 256>>>((const float4*)Wv, (uint2*)Wvh, nW4);
    cvt_kernel<<<(nW4 + 255)/256, 256>>>((const float4*)Wg, (uint2*)Wgh, nW4);

    dim3 grid(DD / BN, NRB);   // (16, 128)
    stats_kernel<<<grid, 256, SMEM_TOTAL>>>(Xh, Wkh, Wvh);
    reduce_stats_kernel<<<(BB * DD + 255) / 256, 256>>>();
    out_kernel<<<grid, 256, SMEM_TOTAL>>>(Xh, Wqh, Wgh, bg, x, out);
}